// round 3
// baseline (speedup 1.0000x reference)
#include <cuda_runtime.h>

// ---------------------------------------------------------------------------
// TransformerBlock: x -> QKV -> full-width attention -> +res LN -> FFN -> +res LN
// B=4, S=2048, D=1024, F=4096, fp32 throughout.
// Strategy: fp32 SIMT GEMM using packed fma.rn.f32x2 (2x fp32 rate on sm_103a),
// 128x128x16 tiles, 8x8 micro-tile per thread, register-prefetch double buffer.
// ---------------------------------------------------------------------------

#define BB 4
#define SS 2048
#define DD 1024
#define FDIM 4096
#define MM (BB * SS) // 8192

// Scratch (static device globals; no allocation anywhere)
__device__ float g_q [MM * DD];
__device__ float g_k [MM * DD];
__device__ float g_v [MM * DD];
__device__ float g_s [BB * SS * SS];
__device__ float g_ctx[MM * DD];
__device__ float g_ao [MM * DD];
__device__ float g_x1 [MM * DD];
__device__ float g_h  [MM * FDIM];
__device__ float g_ff [MM * DD];

// ---- packed f32x2 helpers -------------------------------------------------
__device__ __forceinline__ unsigned long long pk2(float lo, float hi) {
    unsigned long long r;
    asm("mov.b64 %0, {%1, %2};" : "=l"(r) : "f"(lo), "f"(hi));
    return r;
}
__device__ __forceinline__ void upk2(unsigned long long v, float& lo, float& hi) {
    asm("mov.b64 {%0, %1}, %2;" : "=f"(lo), "=f"(hi) : "l"(v));
}
__device__ __forceinline__ unsigned long long fma2(unsigned long long a,
                                                   unsigned long long b,
                                                   unsigned long long c) {
    unsigned long long d;
    asm("fma.rn.f32x2 %0, %1, %2, %3;" : "=l"(d) : "l"(a), "l"(b), "l"(c));
    return d;
}

// ---------------------------------------------------------------------------
// Generic tiled GEMM: C = op(A[M,K] * B) * scale + bias, optional relu.
//   TRANSB=false: B is [K,N] row-major (NN)
//   TRANSB=true : B is [N,K] row-major (NT, C = A * B^T)
// Requires M%128==0, N%128==0, K%16==0 (true for all shapes here).
// grid = (N/128, M/128, batch); batch strides sA/sB/sC in elements.
// ---------------------------------------------------------------------------
template <bool TRANSB>
__global__ void __launch_bounds__(256, 2) gemm128(
    const float* __restrict__ A, const float* __restrict__ B,
    const float* __restrict__ bias, float* __restrict__ C,
    int M, int N, int K,
    long long sA, long long sB, long long sC,
    float scale, int relu)
{
    constexpr int BM = 128, BN = 128, BK = 16;
    __shared__ float As[BK][BM + 4];
    __shared__ float Bs[BK][BN + 4];

    A += (long long)blockIdx.z * sA;
    B += (long long)blockIdx.z * sB;
    C += (long long)blockIdx.z * sC;

    const int tid = threadIdx.x;
    const int tx = tid & 15;       // 0..15 -> 8 cols each
    const int ty = tid >> 4;       // 0..15 -> 8 rows each
    const int rowBase = blockIdx.y * BM;
    const int colBase = blockIdx.x * BN;

    // A-tile loader: 128 rows x 16 k, float4 along K
    const int ar = tid >> 2;           // 0..63
    const int ac = (tid & 3) * 4;      // 0,4,8,12
    const float* Ap0 = A + (size_t)(rowBase + ar) * K + ac;
    const float* Ap1 = Ap0 + (size_t)64 * K;

    // B-tile loader
    const float* Bp0;
    const float* Bp1;
    int br = 0, bc = 0;
    if (TRANSB) {
        Bp0 = B + (size_t)(colBase + ar) * K + ac;
        Bp1 = Bp0 + (size_t)64 * K;
    } else {
        br = tid >> 5;                 // 0..7
        bc = (tid & 31) * 4;           // 0..124
        Bp0 = B + (size_t)br * N + colBase + bc;
        Bp1 = Bp0 + (size_t)8 * N;
    }

    unsigned long long acc[8][4];
#pragma unroll
    for (int i = 0; i < 8; i++)
#pragma unroll
        for (int j = 0; j < 4; j++) acc[i][j] = 0ull;

    float4 ra0, ra1, rb0, rb1;

    auto fetch = [&](int t) {
        ra0 = *(const float4*)(Ap0 + (size_t)t * BK);
        ra1 = *(const float4*)(Ap1 + (size_t)t * BK);
        if (TRANSB) {
            rb0 = *(const float4*)(Bp0 + (size_t)t * BK);
            rb1 = *(const float4*)(Bp1 + (size_t)t * BK);
        } else {
            rb0 = *(const float4*)(Bp0 + (size_t)t * BK * N);
            rb1 = *(const float4*)(Bp1 + (size_t)t * BK * N);
        }
    };
    auto stow = [&]() {
        As[ac + 0][ar] = ra0.x; As[ac + 1][ar] = ra0.y;
        As[ac + 2][ar] = ra0.z; As[ac + 3][ar] = ra0.w;
        As[ac + 0][ar + 64] = ra1.x; As[ac + 1][ar + 64] = ra1.y;
        As[ac + 2][ar + 64] = ra1.z; As[ac + 3][ar + 64] = ra1.w;
        if (TRANSB) {
            Bs[ac + 0][ar] = rb0.x; Bs[ac + 1][ar] = rb0.y;
            Bs[ac + 2][ar] = rb0.z; Bs[ac + 3][ar] = rb0.w;
            Bs[ac + 0][ar + 64] = rb1.x; Bs[ac + 1][ar + 64] = rb1.y;
            Bs[ac + 2][ar + 64] = rb1.z; Bs[ac + 3][ar + 64] = rb1.w;
        } else {
            *(float4*)&Bs[br][bc]     = rb0;
            *(float4*)&Bs[br + 8][bc] = rb1;
        }
    };

    fetch(0);
    stow();
    __syncthreads();

    const int ntiles = K / BK;
    for (int t = 0; t < ntiles; ++t) {
        if (t + 1 < ntiles) fetch(t + 1);

#pragma unroll
        for (int k = 0; k < BK; ++k) {
            float4 a0 = *(const float4*)&As[k][ty * 8];
            float4 a1 = *(const float4*)&As[k][ty * 8 + 4];
            float4 b0 = *(const float4*)&Bs[k][tx * 8];
            float4 b1 = *(const float4*)&Bs[k][tx * 8 + 4];
            unsigned long long bp[4] = { pk2(b0.x, b0.y), pk2(b0.z, b0.w),
                                         pk2(b1.x, b1.y), pk2(b1.z, b1.w) };
            float av[8] = { a0.x, a0.y, a0.z, a0.w, a1.x, a1.y, a1.z, a1.w };
#pragma unroll
            for (int i = 0; i < 8; i++) {
                unsigned long long ai = pk2(av[i], av[i]);
#pragma unroll
                for (int j = 0; j < 4; j++) acc[i][j] = fma2(ai, bp[j], acc[i][j]);
            }
        }
        __syncthreads();
        if (t + 1 < ntiles) { stow(); __syncthreads(); }
    }

    // epilogue
    const int row0 = rowBase + ty * 8;
    const int col0 = colBase + tx * 8;
#pragma unroll
    for (int i = 0; i < 8; i++) {
        float o[8];
#pragma unroll
        for (int j = 0; j < 4; j++) upk2(acc[i][j], o[2 * j], o[2 * j + 1]);
#pragma unroll
        for (int j = 0; j < 8; j++) {
            float val = o[j] * scale;
            if (bias) val += bias[col0 + j];
            if (relu) val = fmaxf(val, 0.0f);
            o[j] = val;
        }
        float4* cp = (float4*)(C + (size_t)(row0 + i) * N + col0);
        cp[0] = make_float4(o[0], o[1], o[2], o[3]);
        cp[1] = make_float4(o[4], o[5], o[6], o[7]);
    }
}

// ---------------------------------------------------------------------------
// Row softmax over width 2048, in place. grid = nrows, block = 256.
// ---------------------------------------------------------------------------
__global__ void __launch_bounds__(256) softmax2048(float* __restrict__ S)
{
    float* p = S + (size_t)blockIdx.x * 2048;
    const int tid = threadIdx.x;
    __shared__ float red[8];

    float v[8];
    float m = -1e30f;
#pragma unroll
    for (int i = 0; i < 8; i++) { v[i] = p[tid + 256 * i]; m = fmaxf(m, v[i]); }
#pragma unroll
    for (int o = 16; o > 0; o >>= 1) m = fmaxf(m, __shfl_xor_sync(0xffffffffu, m, o));
    if ((tid & 31) == 0) red[tid >> 5] = m;
    __syncthreads();
    m = red[0];
#pragma unroll
    for (int i = 1; i < 8; i++) m = fmaxf(m, red[i]);

    float s = 0.0f;
#pragma unroll
    for (int i = 0; i < 8; i++) { v[i] = expf(v[i] - m); s += v[i]; }
#pragma unroll
    for (int o = 16; o > 0; o >>= 1) s += __shfl_xor_sync(0xffffffffu, s, o);
    __syncthreads();                   // red read-before-overwrite
    if ((tid & 31) == 0) red[tid >> 5] = s;
    __syncthreads();
    s = red[0] + red[1] + red[2] + red[3] + red[4] + red[5] + red[6] + red[7];
    const float inv = 1.0f / s;
#pragma unroll
    for (int i = 0; i < 8; i++) p[tid + 256 * i] = v[i] * inv;
}

// ---------------------------------------------------------------------------
// out = LayerNorm(A + B) * g + be, row width 1024. grid = nrows, block = 256.
// ---------------------------------------------------------------------------
__global__ void __launch_bounds__(256) add_ln1024(
    const float* __restrict__ A, const float* __restrict__ Bv,
    const float* __restrict__ g, const float* __restrict__ be,
    float* __restrict__ out)
{
    const size_t base = (size_t)blockIdx.x * 1024;
    const int tid = threadIdx.x;
    __shared__ float r1[8], r2[8];

    float v[4];
    float s = 0.0f, ss = 0.0f;
#pragma unroll
    for (int i = 0; i < 4; i++) {
        const int c = tid + 256 * i;
        v[i] = A[base + c] + Bv[base + c];
        s += v[i];
        ss += v[i] * v[i];
    }
#pragma unroll
    for (int o = 16; o > 0; o >>= 1) {
        s  += __shfl_xor_sync(0xffffffffu, s, o);
        ss += __shfl_xor_sync(0xffffffffu, ss, o);
    }
    if ((tid & 31) == 0) { r1[tid >> 5] = s; r2[tid >> 5] = ss; }
    __syncthreads();
    s = 0.0f; ss = 0.0f;
#pragma unroll
    for (int i = 0; i < 8; i++) { s += r1[i]; ss += r2[i]; }
    const float mean = s * (1.0f / 1024.0f);
    const float var  = ss * (1.0f / 1024.0f) - mean * mean;
    const float rstd = rsqrtf(var + 1e-5f);
#pragma unroll
    for (int i = 0; i < 4; i++) {
        const int c = tid + 256 * i;
        out[base + c] = (v[i] - mean) * rstd * g[c] + be[c];
    }
}

// ---------------------------------------------------------------------------
extern "C" void kernel_launch(void* const* d_in, const int* in_sizes, int n_in,
                              void* d_out, int out_size)
{
    (void)in_sizes; (void)n_in; (void)out_size;
    const float* x   = (const float*)d_in[0];
    const float* wq  = (const float*)d_in[1];
    const float* bq  = (const float*)d_in[2];
    const float* wk  = (const float*)d_in[3];
    const float* bk  = (const float*)d_in[4];
    const float* wv  = (const float*)d_in[5];
    const float* bv  = (const float*)d_in[6];
    const float* wo  = (const float*)d_in[7];
    const float* bo  = (const float*)d_in[8];
    const float* w1  = (const float*)d_in[9];
    const float* b1  = (const float*)d_in[10];
    const float* w2  = (const float*)d_in[11];
    const float* b2  = (const float*)d_in[12];
    const float* g1  = (const float*)d_in[13];
    const float* be1 = (const float*)d_in[14];
    const float* g2  = (const float*)d_in[15];
    const float* be2 = (const float*)d_in[16];
    float* out = (float*)d_out;

    float *q, *k, *v, *sc, *ctx, *ao, *x1, *h, *ff;
    cudaGetSymbolAddress((void**)&q,   g_q);
    cudaGetSymbolAddress((void**)&k,   g_k);
    cudaGetSymbolAddress((void**)&v,   g_v);
    cudaGetSymbolAddress((void**)&sc,  g_s);
    cudaGetSymbolAddress((void**)&ctx, g_ctx);
    cudaGetSymbolAddress((void**)&ao,  g_ao);
    cudaGetSymbolAddress((void**)&x1,  g_x1);
    cudaGetSymbolAddress((void**)&h,   g_h);
    cudaGetSymbolAddress((void**)&ff,  g_ff);

    const dim3 blk(256);

    // Q, K, V projections: [8192,1024] x [1024,1024] + bias
    gemm128<false><<<dim3(DD / 128, MM / 128, 1), blk>>>(x, wq, bq, q, MM, DD, DD, 0, 0, 0, 1.0f, 0);
    gemm128<false><<<dim3(DD / 128, MM / 128, 1), blk>>>(x, wk, bk, k, MM, DD, DD, 0, 0, 0, 1.0f, 0);
    gemm128<false><<<dim3(DD / 128, MM / 128, 1), blk>>>(x, wv, bv, v, MM, DD, DD, 0, 0, 0, 1.0f, 0);

    // scores = Q K^T / sqrt(D), batched over 4
    gemm128<true><<<dim3(SS / 128, SS / 128, BB), blk>>>(
        q, k, nullptr, sc, SS, SS, DD,
        (long long)SS * DD, (long long)SS * DD, (long long)SS * SS, 0.03125f, 0);

    softmax2048<<<BB * SS, 256>>>(sc);

    // ctx = attn @ V, batched
    gemm128<false><<<dim3(DD / 128, SS / 128, BB), blk>>>(
        sc, v, nullptr, ctx, SS, DD, SS,
        (long long)SS * SS, (long long)SS * DD, (long long)SS * DD, 1.0f, 0);

    // attn_out = ctx @ Wo + bo
    gemm128<false><<<dim3(DD / 128, MM / 128, 1), blk>>>(ctx, wo, bo, ao, MM, DD, DD, 0, 0, 0, 1.0f, 0);

    // x1 = LN(x + attn_out)
    add_ln1024<<<MM, 256>>>(x, ao, g1, be1, x1);

    // h = relu(x1 @ W1 + b1)
    gemm128<false><<<dim3(FDIM / 128, MM / 128, 1), blk>>>(x1, w1, b1, h, MM, FDIM, DD, 0, 0, 0, 1.0f, 1);

    // ff = h @ W2 + b2
    gemm128<false><<<dim3(DD / 128, MM / 128, 1), blk>>>(h, w2, b2, ff, MM, DD, FDIM, 0, 0, 0, 1.0f, 0);

    // out = LN(x1 + ff)
    add_ln1024<<<MM, 256>>>(x1, ff, g2, be2, out);
}

// round 4
// speedup vs baseline: 1.0001x; 1.0001x over previous
#include <cuda_runtime.h>

// ---------------------------------------------------------------------------
// TransformerBlock: x -> QKV -> full-width attention -> +res LN -> FFN -> +res LN
// B=4, S=2048, D=1024, F=4096, fp32 throughout.
// Strategy: fp32 SIMT GEMM using packed fma.rn.f32x2 (2x fp32 rate on sm_103a),
// 128x128x16 tiles, 8x8 micro-tile per thread, register-prefetch double buffer.
// ---------------------------------------------------------------------------

#define BB 4
#define SS 2048
#define DD 1024
#define FDIM 4096
#define MM (BB * SS) // 8192

// Scratch (static device globals; no allocation anywhere)
__device__ float g_q [MM * DD];
__device__ float g_k [MM * DD];
__device__ float g_v [MM * DD];
__device__ float g_s [BB * SS * SS];
__device__ float g_ctx[MM * DD];
__device__ float g_ao [MM * DD];
__device__ float g_x1 [MM * DD];
__device__ float g_h  [MM * FDIM];
__device__ float g_ff [MM * DD];

// ---- packed f32x2 helpers -------------------------------------------------
__device__ __forceinline__ unsigned long long pk2(float lo, float hi) {
    unsigned long long r;
    asm("mov.b64 %0, {%1, %2};" : "=l"(r) : "f"(lo), "f"(hi));
    return r;
}
__device__ __forceinline__ void upk2(unsigned long long v, float& lo, float& hi) {
    asm("mov.b64 {%0, %1}, %2;" : "=f"(lo), "=f"(hi) : "l"(v));
}
__device__ __forceinline__ unsigned long long fma2(unsigned long long a,
                                                   unsigned long long b,
                                                   unsigned long long c) {
    unsigned long long d;
    asm("fma.rn.f32x2 %0, %1, %2, %3;" : "=l"(d) : "l"(a), "l"(b), "l"(c));
    return d;
}

// ---------------------------------------------------------------------------
// Generic tiled GEMM: C = op(A[M,K] * B) * scale + bias, optional relu.
//   TRANSB=false: B is [K,N] row-major (NN)
//   TRANSB=true : B is [N,K] row-major (NT, C = A * B^T)
// Requires M%128==0, N%128==0, K%16==0 (true for all shapes here).
// grid = (N/128, M/128, batch); batch strides sA/sB/sC in elements.
// ---------------------------------------------------------------------------
template <bool TRANSB>
__global__ void __launch_bounds__(256, 2) gemm128(
    const float* __restrict__ A, const float* __restrict__ B,
    const float* __restrict__ bias, float* __restrict__ C,
    int M, int N, int K,
    long long sA, long long sB, long long sC,
    float scale, int relu)
{
    constexpr int BM = 128, BN = 128, BK = 16;
    __shared__ float As[BK][BM + 4];
    __shared__ float Bs[BK][BN + 4];

    A += (long long)blockIdx.z * sA;
    B += (long long)blockIdx.z * sB;
    C += (long long)blockIdx.z * sC;

    const int tid = threadIdx.x;
    const int tx = tid & 15;       // 0..15 -> 8 cols each
    const int ty = tid >> 4;       // 0..15 -> 8 rows each
    const int rowBase = blockIdx.y * BM;
    const int colBase = blockIdx.x * BN;

    // A-tile loader: 128 rows x 16 k, float4 along K
    const int ar = tid >> 2;           // 0..63
    const int ac = (tid & 3) * 4;      // 0,4,8,12
    const float* Ap0 = A + (size_t)(rowBase + ar) * K + ac;
    const float* Ap1 = Ap0 + (size_t)64 * K;

    // B-tile loader
    const float* Bp0;
    const float* Bp1;
    int br = 0, bc = 0;
    if (TRANSB) {
        Bp0 = B + (size_t)(colBase + ar) * K + ac;
        Bp1 = Bp0 + (size_t)64 * K;
    } else {
        br = tid >> 5;                 // 0..7
        bc = (tid & 31) * 4;           // 0..124
        Bp0 = B + (size_t)br * N + colBase + bc;
        Bp1 = Bp0 + (size_t)8 * N;
    }

    unsigned long long acc[8][4];
#pragma unroll
    for (int i = 0; i < 8; i++)
#pragma unroll
        for (int j = 0; j < 4; j++) acc[i][j] = 0ull;

    float4 ra0, ra1, rb0, rb1;

    auto fetch = [&](int t) {
        ra0 = *(const float4*)(Ap0 + (size_t)t * BK);
        ra1 = *(const float4*)(Ap1 + (size_t)t * BK);
        if (TRANSB) {
            rb0 = *(const float4*)(Bp0 + (size_t)t * BK);
            rb1 = *(const float4*)(Bp1 + (size_t)t * BK);
        } else {
            rb0 = *(const float4*)(Bp0 + (size_t)t * BK * N);
            rb1 = *(const float4*)(Bp1 + (size_t)t * BK * N);
        }
    };
    auto stow = [&]() {
        As[ac + 0][ar] = ra0.x; As[ac + 1][ar] = ra0.y;
        As[ac + 2][ar] = ra0.z; As[ac + 3][ar] = ra0.w;
        As[ac + 0][ar + 64] = ra1.x; As[ac + 1][ar + 64] = ra1.y;
        As[ac + 2][ar + 64] = ra1.z; As[ac + 3][ar + 64] = ra1.w;
        if (TRANSB) {
            Bs[ac + 0][ar] = rb0.x; Bs[ac + 1][ar] = rb0.y;
            Bs[ac + 2][ar] = rb0.z; Bs[ac + 3][ar] = rb0.w;
            Bs[ac + 0][ar + 64] = rb1.x; Bs[ac + 1][ar + 64] = rb1.y;
            Bs[ac + 2][ar + 64] = rb1.z; Bs[ac + 3][ar + 64] = rb1.w;
        } else {
            *(float4*)&Bs[br][bc]     = rb0;
            *(float4*)&Bs[br + 8][bc] = rb1;
        }
    };

    fetch(0);
    stow();
    __syncthreads();

    const int ntiles = K / BK;
    for (int t = 0; t < ntiles; ++t) {
        if (t + 1 < ntiles) fetch(t + 1);

#pragma unroll
        for (int k = 0; k < BK; ++k) {
            float4 a0 = *(const float4*)&As[k][ty * 8];
            float4 a1 = *(const float4*)&As[k][ty * 8 + 4];
            float4 b0 = *(const float4*)&Bs[k][tx * 8];
            float4 b1 = *(const float4*)&Bs[k][tx * 8 + 4];
            unsigned long long bp[4] = { pk2(b0.x, b0.y), pk2(b0.z, b0.w),
                                         pk2(b1.x, b1.y), pk2(b1.z, b1.w) };
            float av[8] = { a0.x, a0.y, a0.z, a0.w, a1.x, a1.y, a1.z, a1.w };
#pragma unroll
            for (int i = 0; i < 8; i++) {
                unsigned long long ai = pk2(av[i], av[i]);
#pragma unroll
                for (int j = 0; j < 4; j++) acc[i][j] = fma2(ai, bp[j], acc[i][j]);
            }
        }
        __syncthreads();
        if (t + 1 < ntiles) { stow(); __syncthreads(); }
    }

    // epilogue
    const int row0 = rowBase + ty * 8;
    const int col0 = colBase + tx * 8;
#pragma unroll
    for (int i = 0; i < 8; i++) {
        float o[8];
#pragma unroll
        for (int j = 0; j < 4; j++) upk2(acc[i][j], o[2 * j], o[2 * j + 1]);
#pragma unroll
        for (int j = 0; j < 8; j++) {
            float val = o[j] * scale;
            if (bias) val += bias[col0 + j];
            if (relu) val = fmaxf(val, 0.0f);
            o[j] = val;
        }
        float4* cp = (float4*)(C + (size_t)(row0 + i) * N + col0);
        cp[0] = make_float4(o[0], o[1], o[2], o[3]);
        cp[1] = make_float4(o[4], o[5], o[6], o[7]);
    }
}

// ---------------------------------------------------------------------------
// Row softmax over width 2048, in place. grid = nrows, block = 256.
// ---------------------------------------------------------------------------
__global__ void __launch_bounds__(256) softmax2048(float* __restrict__ S)
{
    float* p = S + (size_t)blockIdx.x * 2048;
    const int tid = threadIdx.x;
    __shared__ float red[8];

    float v[8];
    float m = -1e30f;
#pragma unroll
    for (int i = 0; i < 8; i++) { v[i] = p[tid + 256 * i]; m = fmaxf(m, v[i]); }
#pragma unroll
    for (int o = 16; o > 0; o >>= 1) m = fmaxf(m, __shfl_xor_sync(0xffffffffu, m, o));
    if ((tid & 31) == 0) red[tid >> 5] = m;
    __syncthreads();
    m = red[0];
#pragma unroll
    for (int i = 1; i < 8; i++) m = fmaxf(m, red[i]);

    float s = 0.0f;
#pragma unroll
    for (int i = 0; i < 8; i++) { v[i] = expf(v[i] - m); s += v[i]; }
#pragma unroll
    for (int o = 16; o > 0; o >>= 1) s += __shfl_xor_sync(0xffffffffu, s, o);
    __syncthreads();                   // red read-before-overwrite
    if ((tid & 31) == 0) red[tid >> 5] = s;
    __syncthreads();
    s = red[0] + red[1] + red[2] + red[3] + red[4] + red[5] + red[6] + red[7];
    const float inv = 1.0f / s;
#pragma unroll
    for (int i = 0; i < 8; i++) p[tid + 256 * i] = v[i] * inv;
}

// ---------------------------------------------------------------------------
// out = LayerNorm(A + B) * g + be, row width 1024. grid = nrows, block = 256.
// ---------------------------------------------------------------------------
__global__ void __launch_bounds__(256) add_ln1024(
    const float* __restrict__ A, const float* __restrict__ Bv,
    const float* __restrict__ g, const float* __restrict__ be,
    float* __restrict__ out)
{
    const size_t base = (size_t)blockIdx.x * 1024;
    const int tid = threadIdx.x;
    __shared__ float r1[8], r2[8];

    float v[4];
    float s = 0.0f, ss = 0.0f;
#pragma unroll
    for (int i = 0; i < 4; i++) {
        const int c = tid + 256 * i;
        v[i] = A[base + c] + Bv[base + c];
        s += v[i];
        ss += v[i] * v[i];
    }
#pragma unroll
    for (int o = 16; o > 0; o >>= 1) {
        s  += __shfl_xor_sync(0xffffffffu, s, o);
        ss += __shfl_xor_sync(0xffffffffu, ss, o);
    }
    if ((tid & 31) == 0) { r1[tid >> 5] = s; r2[tid >> 5] = ss; }
    __syncthreads();
    s = 0.0f; ss = 0.0f;
#pragma unroll
    for (int i = 0; i < 8; i++) { s += r1[i]; ss += r2[i]; }
    const float mean = s * (1.0f / 1024.0f);
    const float var  = ss * (1.0f / 1024.0f) - mean * mean;
    const float rstd = rsqrtf(var + 1e-5f);
#pragma unroll
    for (int i = 0; i < 4; i++) {
        const int c = tid + 256 * i;
        out[base + c] = (v[i] - mean) * rstd * g[c] + be[c];
    }
}

// ---------------------------------------------------------------------------
extern "C" void kernel_launch(void* const* d_in, const int* in_sizes, int n_in,
                              void* d_out, int out_size)
{
    (void)in_sizes; (void)n_in; (void)out_size;
    const float* x   = (const float*)d_in[0];
    const float* wq  = (const float*)d_in[1];
    const float* bq  = (const float*)d_in[2];
    const float* wk  = (const float*)d_in[3];
    const float* bk  = (const float*)d_in[4];
    const float* wv  = (const float*)d_in[5];
    const float* bv  = (const float*)d_in[6];
    const float* wo  = (const float*)d_in[7];
    const float* bo  = (const float*)d_in[8];
    const float* w1  = (const float*)d_in[9];
    const float* b1  = (const float*)d_in[10];
    const float* w2  = (const float*)d_in[11];
    const float* b2  = (const float*)d_in[12];
    const float* g1  = (const float*)d_in[13];
    const float* be1 = (const float*)d_in[14];
    const float* g2  = (const float*)d_in[15];
    const float* be2 = (const float*)d_in[16];
    float* out = (float*)d_out;

    float *q, *k, *v, *sc, *ctx, *ao, *x1, *h, *ff;
    cudaGetSymbolAddress((void**)&q,   g_q);
    cudaGetSymbolAddress((void**)&k,   g_k);
    cudaGetSymbolAddress((void**)&v,   g_v);
    cudaGetSymbolAddress((void**)&sc,  g_s);
    cudaGetSymbolAddress((void**)&ctx, g_ctx);
    cudaGetSymbolAddress((void**)&ao,  g_ao);
    cudaGetSymbolAddress((void**)&x1,  g_x1);
    cudaGetSymbolAddress((void**)&h,   g_h);
    cudaGetSymbolAddress((void**)&ff,  g_ff);

    const dim3 blk(256);

    // Q, K, V projections: [8192,1024] x [1024,1024] + bias
    gemm128<false><<<dim3(DD / 128, MM / 128, 1), blk>>>(x, wq, bq, q, MM, DD, DD, 0, 0, 0, 1.0f, 0);
    gemm128<false><<<dim3(DD / 128, MM / 128, 1), blk>>>(x, wk, bk, k, MM, DD, DD, 0, 0, 0, 1.0f, 0);
    gemm128<false><<<dim3(DD / 128, MM / 128, 1), blk>>>(x, wv, bv, v, MM, DD, DD, 0, 0, 0, 1.0f, 0);

    // scores = Q K^T / sqrt(D), batched over 4
    gemm128<true><<<dim3(SS / 128, SS / 128, BB), blk>>>(
        q, k, nullptr, sc, SS, SS, DD,
        (long long)SS * DD, (long long)SS * DD, (long long)SS * SS, 0.03125f, 0);

    softmax2048<<<BB * SS, 256>>>(sc);

    // ctx = attn @ V, batched
    gemm128<false><<<dim3(DD / 128, SS / 128, BB), blk>>>(
        sc, v, nullptr, ctx, SS, DD, SS,
        (long long)SS * SS, (long long)SS * DD, (long long)SS * DD, 1.0f, 0);

    // attn_out = ctx @ Wo + bo
    gemm128<false><<<dim3(DD / 128, MM / 128, 1), blk>>>(ctx, wo, bo, ao, MM, DD, DD, 0, 0, 0, 1.0f, 0);

    // x1 = LN(x + attn_out)
    add_ln1024<<<MM, 256>>>(x, ao, g1, be1, x1);

    // h = relu(x1 @ W1 + b1)
    gemm128<false><<<dim3(FDIM / 128, MM / 128, 1), blk>>>(x1, w1, b1, h, MM, FDIM, DD, 0, 0, 0, 1.0f, 1);

    // ff = h @ W2 + b2
    gemm128<false><<<dim3(DD / 128, MM / 128, 1), blk>>>(h, w2, b2, ff, MM, DD, FDIM, 0, 0, 0, 1.0f, 0);

    // out = LN(x1 + ff)
    add_ln1024<<<MM, 256>>>(x1, ff, g2, be2, out);
}

// round 8
// speedup vs baseline: 2.7481x; 2.7478x over previous
#include <cuda_runtime.h>
#include <cuda_bf16.h>
#include <cstdint>

typedef __nv_bfloat16 bf16;
typedef unsigned int u32;
typedef unsigned long long u64;

#define BB 4
#define SS 2048
#define DD 1024
#define FF 4096
#define MM (BB * SS)

// ---------------- static device scratch (no allocations) -------------------
__device__ bf16 g_xh[MM*DD], g_xl[MM*DD];
__device__ bf16 g_wqh[DD*DD], g_wql[DD*DD], g_wkh[DD*DD], g_wkl[DD*DD];
__device__ bf16 g_wvh[DD*DD], g_wvl[DD*DD], g_woh[DD*DD], g_wol[DD*DD];
__device__ bf16 g_w1h[(size_t)DD*FF], g_w1l[(size_t)DD*FF];
__device__ bf16 g_w2h[(size_t)FF*DD], g_w2l[(size_t)FF*DD];
__device__ bf16 g_qh[MM*DD], g_ql[MM*DD], g_kh[MM*DD], g_kl[MM*DD];
__device__ float g_v[MM*DD];
__device__ bf16 g_vth[MM*DD], g_vtl[MM*DD];
__device__ float g_sc[(size_t)BB*SS*SS];
__device__ bf16 g_Ph[(size_t)BB*SS*SS], g_Pl[(size_t)BB*SS*SS];
__device__ bf16 g_ch[MM*DD], g_cl[MM*DD];
__device__ float g_ao[MM*DD], g_x1[MM*DD];
__device__ bf16 g_x1h[MM*DD], g_x1l[MM*DD];
__device__ bf16 g_hh[(size_t)MM*FF], g_hl[(size_t)MM*FF];
__device__ float g_ffo[MM*DD];

// ---------------- PTX helpers (base ISA only — compute_103-safe) ------------
__device__ __forceinline__ u32 smem_u32(const void* p) {
    u32 r;
    asm("{ .reg .u64 t; cvta.to.shared.u64 t, %1; cvt.u32.u64 %0, t; }" : "=r"(r) : "l"(p));
    return r;
}
__device__ __forceinline__ void cpa16(u32 d, const void* s) {
    asm volatile("cp.async.cg.shared.global [%0], [%1], 16;" :: "r"(d), "l"(s));
}
__device__ __forceinline__ void cpa_commit() { asm volatile("cp.async.commit_group;" ::: "memory"); }
template <int W> __device__ __forceinline__ void cpa_wait() {
    asm volatile("cp.async.wait_group %0;" :: "n"(W) : "memory");
}
__device__ __forceinline__ void ldsm4(u32& r0, u32& r1, u32& r2, u32& r3, u32 a) {
    asm volatile("ldmatrix.sync.aligned.m8n8.x4.shared.b16 {%0,%1,%2,%3}, [%4];"
        : "=r"(r0), "=r"(r1), "=r"(r2), "=r"(r3) : "r"(a));
}
__device__ __forceinline__ void mma16816(float* d, const u32* a, const u32* b) {
    asm volatile("mma.sync.aligned.m16n8k16.row.col.f32.bf16.bf16.f32 "
        "{%0,%1,%2,%3},{%4,%5,%6,%7},{%8,%9},{%0,%1,%2,%3};"
        : "+f"(d[0]), "+f"(d[1]), "+f"(d[2]), "+f"(d[3])
        : "r"(a[0]), "r"(a[1]), "r"(a[2]), "r"(a[3]), "r"(b[0]), "r"(b[1]));
}
__device__ __forceinline__ void split2(float a, float b, u32& hp, u32& lp) {
    bf16 h0 = __float2bfloat16(a), h1 = __float2bfloat16(b);
    bf16 l0 = __float2bfloat16(a - __bfloat162float(h0));
    bf16 l1 = __float2bfloat16(b - __bfloat162float(h1));
    hp = (u32)__bfloat16_as_ushort(h0) | ((u32)__bfloat16_as_ushort(h1) << 16);
    lp = (u32)__bfloat16_as_ushort(l0) | ((u32)__bfloat16_as_ushort(l1) << 16);
}

// ---------------------------------------------------------------------------
// mma.sync GEMM: C[M,N] = A[M,K] * B[N,K]^T, operands bf16 hi/lo pairs,
// 3-term compensation (AhBh + AhBl + AlBh), fp32 accum.
// Block 128x128, BK=64 (128B swizzled rows), 8 warps x (64x32) warp tiles,
// 3-stage cp.async pipeline. grid=(N/128, M/128, batch).
// ---------------------------------------------------------------------------
#define GTPB 256
#define NSTAGE 3
#define STG 65536                    // Ah 16K | Al 16K | Bh 16K | Bl 16K
#define SMEM_TOTAL (NSTAGE * STG)    // 192 KB

__global__ void __launch_bounds__(GTPB, 1) gemm_mma(
    const bf16* __restrict__ Ah, const bf16* __restrict__ Al,
    const bf16* __restrict__ Bh, const bf16* __restrict__ Bl,
    const float* __restrict__ bias,
    float* __restrict__ outF, bf16* __restrict__ outH, bf16* __restrict__ outL,
    int N, int K, long long sA, long long sB, long long sC,
    float scale, int relu)
{
    extern __shared__ __align__(1024) char smem[];
    const u32 sb = smem_u32(smem);
    const int tid = threadIdx.x;
    const int wid = tid >> 5, lane = tid & 31;

    const long long zb = blockIdx.z;
    const long long rowBase = (long long)blockIdx.y * 128;
    const long long colBase = (long long)blockIdx.x * 128;
    const bf16* Arh = Ah + zb * sA + rowBase * K;
    const bf16* Arl = Al + zb * sA + rowBase * K;
    const bf16* Brh = Bh + zb * sB + colBase * K;
    const bf16* Brl = Bl + zb * sB + colBase * K;
    const int nt = K >> 6;

    // fill one 64KB stage: 4 tiles x 128 rows x 128B, 16B/cp.async, swizzled
    auto fill = [&](int t) {
        const u32 base = sb + (u32)(t % NSTAGE) * STG;
        const long long kof = (long long)t * 64;
#pragma unroll
        for (int i = 0; i < 4; i++) {
            const int c = tid + i * GTPB;          // 0..1023
            const int row = c >> 3, kc = c & 7;    // row 0..127, 16B col 0..7
            const u32 so = (u32)row * 128 + (((u32)kc * 16) ^ (((u32)row & 7) * 16));
            const long long g = (long long)row * K + kof + kc * 8;
            cpa16(base + so,          Arh + g);
            cpa16(base + 16384 + so,  Arl + g);
            cpa16(base + 32768 + so,  Brh + g);
            cpa16(base + 49152 + so,  Brl + g);
        }
    };

    fill(0); cpa_commit();
    fill(1); cpa_commit();

    float acc[4][4][4];
#pragma unroll
    for (int i = 0; i < 4; i++)
#pragma unroll
        for (int j = 0; j < 4; j++)
#pragma unroll
            for (int k = 0; k < 4; k++) acc[i][j][k] = 0.0f;

    const int mw = (wid >> 2) * 64;   // warp row offset (2 groups)
    const int nw = (wid & 3) * 32;    // warp col offset (4 groups)

    for (int t = 0; t < nt; t++) {
        if (t + 1 < nt) cpa_wait<1>(); else cpa_wait<0>();
        __syncthreads();                       // stage t visible; prev stage free
        if (t + 2 < nt) { fill(t + 2); cpa_commit(); }

        const u32 base = sb + (u32)(t % NSTAGE) * STG;
#pragma unroll
        for (int k16 = 0; k16 < 4; k16++) {
            const u32 kb = (u32)k16 * 32;      // byte col of this k16
            // A fragments (hi & lo): 4 m16 tiles
            u32 ah[4][4], al[4][4];
#pragma unroll
            for (int mi = 0; mi < 4; mi++) {
                const u32 row = (u32)(mw + mi * 16 + (lane & 15));
                const u32 kbyte = kb + ((u32)(lane >> 4) << 4);
                const u32 ad = base + row * 128 + (kbyte ^ ((row & 7) << 4));
                ldsm4(ah[mi][0], ah[mi][1], ah[mi][2], ah[mi][3], ad);
                ldsm4(al[mi][0], al[mi][1], al[mi][2], al[mi][3], ad + 16384);
            }
            // B fragments (hi & lo): 4 n8 tiles via 2 x4-loads
            u32 bh[4][2], bl[4][2];
#pragma unroll
            for (int nj = 0; nj < 2; nj++) {
                const u32 g = (u32)(lane >> 3);
                const u32 nrow = (u32)(nw + nj * 16) + ((g >> 1) << 3) + (u32)(lane & 7);
                const u32 kbyte = kb + ((g & 1) << 4);
                const u32 bd = base + 32768 + nrow * 128 + (kbyte ^ ((nrow & 7) << 4));
                u32 q0, q1, q2, q3;
                ldsm4(q0, q1, q2, q3, bd);
                bh[nj*2][0] = q0; bh[nj*2][1] = q1; bh[nj*2+1][0] = q2; bh[nj*2+1][1] = q3;
                ldsm4(q0, q1, q2, q3, bd + 16384);
                bl[nj*2][0] = q0; bl[nj*2][1] = q1; bl[nj*2+1][0] = q2; bl[nj*2+1][1] = q3;
            }
            // 48 MMAs, term-outermost (acc reuse distance 16)
#pragma unroll
            for (int mi = 0; mi < 4; mi++)
#pragma unroll
                for (int ni = 0; ni < 4; ni++) mma16816(acc[mi][ni], ah[mi], bh[ni]);
#pragma unroll
            for (int mi = 0; mi < 4; mi++)
#pragma unroll
                for (int ni = 0; ni < 4; ni++) mma16816(acc[mi][ni], ah[mi], bl[ni]);
#pragma unroll
            for (int mi = 0; mi < 4; mi++)
#pragma unroll
                for (int ni = 0; ni < 4; ni++) mma16816(acc[mi][ni], al[mi], bh[ni]);
        }
    }

    // ---- epilogue ----
    float* ofz = outF ? outF + zb * sC : (float*)0;
    bf16*  ohz = outH ? outH + zb * sC : (bf16*)0;
    bf16*  olz = outL ? outL + zb * sC : (bf16*)0;
#pragma unroll
    for (int mi = 0; mi < 4; mi++) {
#pragma unroll
        for (int ni = 0; ni < 4; ni++) {
            const long long r0 = rowBase + mw + mi * 16 + (lane >> 2);
            const long long c0 = colBase + nw + ni * 8 + (lane & 3) * 2;
            float b0 = 0.0f, b1 = 0.0f;
            if (bias) { b0 = __ldg(bias + c0); b1 = __ldg(bias + c0 + 1); }
#pragma unroll
            for (int h = 0; h < 2; h++) {
                float v0 = acc[mi][ni][2*h]   * scale + b0;
                float v1 = acc[mi][ni][2*h+1] * scale + b1;
                if (relu) { v0 = fmaxf(v0, 0.0f); v1 = fmaxf(v1, 0.0f); }
                const long long off = (r0 + 8 * h) * N + c0;
                if (ofz) *(float2*)(ofz + off) = make_float2(v0, v1);
                if (ohz) {
                    u32 hp, lp; split2(v0, v1, hp, lp);
                    *(u32*)(ohz + off) = hp;
                    *(u32*)(olz + off) = lp;
                }
            }
        }
    }
}

// ---------------- elementwise kernels --------------------------------------
__global__ void __launch_bounds__(256) split_plain(
    const float4* __restrict__ in, bf16* __restrict__ oh, bf16* __restrict__ ol, int n4)
{
    const int i = blockIdx.x * 256 + threadIdx.x;
    if (i >= n4) return;
    float4 x = in[i];
    u32 h0, l0, h1, l1;
    split2(x.x, x.y, h0, l0); split2(x.z, x.w, h1, l1);
    *(uint2*)(oh + 4 * (size_t)i) = make_uint2(h0, h1);
    *(uint2*)(ol + 4 * (size_t)i) = make_uint2(l0, l1);
}

// in [R,C] fp32 -> out [C,R] bf16 hi/lo. grid (C/32, R/32, batch), 256 thr.
__global__ void __launch_bounds__(256) transpose_split(
    const float* __restrict__ in, bf16* __restrict__ oh, bf16* __restrict__ ol,
    int R, int C, long long sIn, long long sOut)
{
    __shared__ float t[32][33];
    in += (long long)blockIdx.z * sIn;
    oh += (long long)blockIdx.z * sOut;
    ol += (long long)blockIdx.z * sOut;
    const int r0 = blockIdx.y * 32, c0 = blockIdx.x * 32;
    const int tx = threadIdx.x & 31, ty = threadIdx.x >> 5;
#pragma unroll
    for (int i = 0; i < 32; i += 8)
        t[ty + i][tx] = in[(long long)(r0 + ty + i) * C + c0 + tx];
    __syncthreads();
#pragma unroll
    for (int i = 0; i < 32; i += 8) {
        float v = t[tx][ty + i];
        bf16 h = __float2bfloat16(v);
        const long long o = (long long)(c0 + ty + i) * R + r0 + tx;
        oh[o] = h; ol[o] = __float2bfloat16(v - __bfloat162float(h));
    }
}

// row softmax over 2048 -> bf16 hi/lo. grid = nrows, block = 256.
__global__ void __launch_bounds__(256) softmax_split(
    const float* __restrict__ S, bf16* __restrict__ Ph, bf16* __restrict__ Pl)
{
    const float* p = S + (size_t)blockIdx.x * 2048;
    bf16* ph = Ph + (size_t)blockIdx.x * 2048;
    bf16* pl = Pl + (size_t)blockIdx.x * 2048;
    const int tid = threadIdx.x;
    __shared__ float red[8];
    float v[8], m = -1e30f;
#pragma unroll
    for (int i = 0; i < 8; i++) { v[i] = p[tid + 256 * i]; m = fmaxf(m, v[i]); }
#pragma unroll
    for (int o = 16; o > 0; o >>= 1) m = fmaxf(m, __shfl_xor_sync(~0u, m, o));
    if ((tid & 31) == 0) red[tid >> 5] = m;
    __syncthreads();
    m = red[0];
#pragma unroll
    for (int i = 1; i < 8; i++) m = fmaxf(m, red[i]);
    float s = 0.0f;
#pragma unroll
    for (int i = 0; i < 8; i++) { v[i] = expf(v[i] - m); s += v[i]; }
#pragma unroll
    for (int o = 16; o > 0; o >>= 1) s += __shfl_xor_sync(~0u, s, o);
    __syncthreads();
    if ((tid & 31) == 0) red[tid >> 5] = s;
    __syncthreads();
    s = red[0]+red[1]+red[2]+red[3]+red[4]+red[5]+red[6]+red[7];
    const float inv = 1.0f / s;
#pragma unroll
    for (int i = 0; i < 8; i++) {
        float x = v[i] * inv;
        bf16 h = __float2bfloat16(x);
        ph[tid + 256 * i] = h;
        pl[tid + 256 * i] = __float2bfloat16(x - __bfloat162float(h));
    }
}

// out = LN(A+B)*g+be (fp32, optional hi/lo). grid = nrows (width 1024).
__global__ void __launch_bounds__(256) add_ln(
    const float* __restrict__ A, const float* __restrict__ Bv,
    const float* __restrict__ g, const float* __restrict__ be,
    float* __restrict__ outF, bf16* __restrict__ oh, bf16* __restrict__ ol)
{
    const size_t base = (size_t)blockIdx.x * 1024;
    const int tid = threadIdx.x;
    __shared__ float r1[8], r2[8];
    float v[4], s = 0.0f, ss = 0.0f;
#pragma unroll
    for (int i = 0; i < 4; i++) {
        const int c = tid + 256 * i;
        v[i] = A[base + c] + Bv[base + c];
        s += v[i]; ss += v[i] * v[i];
    }
#pragma unroll
    for (int o = 16; o > 0; o >>= 1) {
        s  += __shfl_xor_sync(~0u, s, o);
        ss += __shfl_xor_sync(~0u, ss, o);
    }
    if ((tid & 31) == 0) { r1[tid >> 5] = s; r2[tid >> 5] = ss; }
    __syncthreads();
    s = 0.0f; ss = 0.0f;
#pragma unroll
    for (int i = 0; i < 8; i++) { s += r1[i]; ss += r2[i]; }
    const float mean = s * (1.0f / 1024.0f);
    const float rstd = rsqrtf(ss * (1.0f / 1024.0f) - mean * mean + 1e-5f);
#pragma unroll
    for (int i = 0; i < 4; i++) {
        const int c = tid + 256 * i;
        const float x = (v[i] - mean) * rstd * g[c] + be[c];
        outF[base + c] = x;
        if (oh) {
            bf16 h = __float2bfloat16(x);
            oh[base + c] = h;
            ol[base + c] = __float2bfloat16(x - __bfloat162float(h));
        }
    }
}

// ---------------------------------------------------------------------------
extern "C" void kernel_launch(void* const* d_in, const int* in_sizes, int n_in,
                              void* d_out, int out_size)
{
    (void)in_sizes; (void)n_in; (void)out_size;
    const float* x   = (const float*)d_in[0];
    const float* wq  = (const float*)d_in[1];  const float* bq = (const float*)d_in[2];
    const float* wk  = (const float*)d_in[3];  const float* bk = (const float*)d_in[4];
    const float* wv  = (const float*)d_in[5];  const float* bv = (const float*)d_in[6];
    const float* wo  = (const float*)d_in[7];  const float* bo = (const float*)d_in[8];
    const float* w1  = (const float*)d_in[9];  const float* b1 = (const float*)d_in[10];
    const float* w2  = (const float*)d_in[11]; const float* b2 = (const float*)d_in[12];
    const float* g1  = (const float*)d_in[13]; const float* be1 = (const float*)d_in[14];
    const float* g2  = (const float*)d_in[15]; const float* be2 = (const float*)d_in[16];
    float* out = (float*)d_out;

#define SYM(nm, s) void* nm; cudaGetSymbolAddress(&nm, s)
    SYM(xh, g_xh); SYM(xl, g_xl);
    SYM(wqh, g_wqh); SYM(wql, g_wql); SYM(wkh, g_wkh); SYM(wkl, g_wkl);
    SYM(wvh, g_wvh); SYM(wvl, g_wvl); SYM(woh, g_woh); SYM(wol, g_wol);
    SYM(w1h, g_w1h); SYM(w1l, g_w1l); SYM(w2h, g_w2h); SYM(w2l, g_w2l);
    SYM(qh, g_qh); SYM(ql, g_ql); SYM(kh, g_kh); SYM(kl, g_kl);
    SYM(v, g_v); SYM(vth, g_vth); SYM(vtl, g_vtl);
    SYM(sc, g_sc); SYM(Ph, g_Ph); SYM(Pl, g_Pl);
    SYM(ch, g_ch); SYM(cl, g_cl);
    SYM(ao, g_ao); SYM(x1, g_x1); SYM(x1h, g_x1h); SYM(x1l, g_x1l);
    SYM(hh, g_hh); SYM(hl, g_hl); SYM(ffo, g_ffo);
#undef SYM
#define Fo(p) ((float*)p)
#define Hh(p) ((bf16*)p)

    cudaFuncSetAttribute(gemm_mma, cudaFuncAttributeMaxDynamicSharedMemorySize, SMEM_TOTAL);

    // operand prep: x split; weights transposed+split to [N,K]
    split_plain<<<MM * DD / 4 / 256, 256>>>((const float4*)x, Hh(xh), Hh(xl), MM * DD / 4);
    transpose_split<<<dim3(DD/32, DD/32, 1), 256>>>(wq, Hh(wqh), Hh(wql), DD, DD, 0, 0);
    transpose_split<<<dim3(DD/32, DD/32, 1), 256>>>(wk, Hh(wkh), Hh(wkl), DD, DD, 0, 0);
    transpose_split<<<dim3(DD/32, DD/32, 1), 256>>>(wv, Hh(wvh), Hh(wvl), DD, DD, 0, 0);
    transpose_split<<<dim3(DD/32, DD/32, 1), 256>>>(wo, Hh(woh), Hh(wol), DD, DD, 0, 0);
    transpose_split<<<dim3(FF/32, DD/32, 1), 256>>>(w1, Hh(w1h), Hh(w1l), DD, FF, 0, 0);
    transpose_split<<<dim3(DD/32, FF/32, 1), 256>>>(w2, Hh(w2h), Hh(w2l), FF, DD, 0, 0);

    const dim3 gq(DD/128, MM/128, 1);
    // QKV projections (Q,K -> bf16 split; V -> fp32 then transpose-split)
    gemm_mma<<<gq, GTPB, SMEM_TOTAL>>>(Hh(xh), Hh(xl), Hh(wqh), Hh(wql), bq,
        (float*)0, Hh(qh), Hh(ql), DD, DD, 0, 0, 0, 1.0f, 0);
    gemm_mma<<<gq, GTPB, SMEM_TOTAL>>>(Hh(xh), Hh(xl), Hh(wkh), Hh(wkl), bk,
        (float*)0, Hh(kh), Hh(kl), DD, DD, 0, 0, 0, 1.0f, 0);
    gemm_mma<<<gq, GTPB, SMEM_TOTAL>>>(Hh(xh), Hh(xl), Hh(wvh), Hh(wvl), bv,
        Fo(v), (bf16*)0, (bf16*)0, DD, DD, 0, 0, 0, 1.0f, 0);
    transpose_split<<<dim3(DD/32, SS/32, BB), 256>>>(Fo(v), Hh(vth), Hh(vtl),
        SS, DD, (long long)SS*DD, (long long)SS*DD);

    // scores = Q K^T / 32
    gemm_mma<<<dim3(SS/128, SS/128, BB), GTPB, SMEM_TOTAL>>>(
        Hh(qh), Hh(ql), Hh(kh), Hh(kl), (const float*)0,
        Fo(sc), (bf16*)0, (bf16*)0, SS, DD,
        (long long)SS*DD, (long long)SS*DD, (long long)SS*SS, 0.03125f, 0);

    softmax_split<<<BB * SS, 256>>>(Fo(sc), Hh(Ph), Hh(Pl));

    // ctx = P @ V   (B = V^T [D,S])
    gemm_mma<<<dim3(DD/128, SS/128, BB), GTPB, SMEM_TOTAL>>>(
        Hh(Ph), Hh(Pl), Hh(vth), Hh(vtl), (const float*)0,
        (float*)0, Hh(ch), Hh(cl), DD, SS,
        (long long)SS*SS, (long long)SS*DD, (long long)SS*DD, 1.0f, 0);

    // attn_out = ctx @ Wo + bo
    gemm_mma<<<gq, GTPB, SMEM_TOTAL>>>(Hh(ch), Hh(cl), Hh(woh), Hh(wol), bo,
        Fo(ao), (bf16*)0, (bf16*)0, DD, DD, 0, 0, 0, 1.0f, 0);

    // x1 = LN(x + attn_out)
    add_ln<<<MM, 256>>>(x, Fo(ao), g1, be1, Fo(x1), Hh(x1h), Hh(x1l));

    // h = relu(x1 @ W1 + b1)
    gemm_mma<<<dim3(FF/128, MM/128, 1), GTPB, SMEM_TOTAL>>>(
        Hh(x1h), Hh(x1l), Hh(w1h), Hh(w1l), b1,
        (float*)0, Hh(hh), Hh(hl), FF, DD, 0, 0, 0, 1.0f, 1);

    // ff = h @ W2 + b2
    gemm_mma<<<gq, GTPB, SMEM_TOTAL>>>(Hh(hh), Hh(hl), Hh(w2h), Hh(w2l), b2,
        Fo(ffo), (bf16*)0, (bf16*)0, DD, FF, 0, 0, 0, 1.0f, 0);

    // out = LN(x1 + ff)
    add_ln<<<MM, 256>>>(Fo(x1), Fo(ffo), g2, be2, out, (bf16*)0, (bf16*)0);
}

// round 9
// speedup vs baseline: 7.1463x; 2.6005x over previous
#include <cuda_runtime.h>
#include <cuda_fp16.h>
#include <cstdint>

typedef __half fp16;
typedef unsigned int u32;
typedef unsigned long long u64;

#define BB 4
#define SS 2048
#define DD 1024
#define FF 4096
#define MM (BB * SS)

// ---------------- static device scratch (no allocations) -------------------
__device__ fp16 g_x16[MM*DD];
__device__ fp16 g_wq16[DD*DD], g_wk16[DD*DD], g_wv16[DD*DD], g_wo16[DD*DD];
__device__ fp16 g_w116[(size_t)DD*FF], g_w216[(size_t)FF*DD];
__device__ fp16 g_q16[MM*DD], g_k16[MM*DD];
__device__ float g_v[MM*DD];
__device__ fp16 g_vt16[MM*DD];
__device__ float g_sc[(size_t)BB*SS*SS];
__device__ fp16 g_P16[(size_t)BB*SS*SS];
__device__ fp16 g_c16[MM*DD];
__device__ float g_ao[MM*DD], g_x1[MM*DD];
__device__ fp16 g_x116[MM*DD];
__device__ fp16 g_h16[(size_t)MM*FF];
__device__ float g_ffo[MM*DD];

// ---------------- PTX helpers (base ISA — compute_103-safe) -----------------
__device__ __forceinline__ u32 smem_u32(const void* p) {
    u32 r;
    asm("{ .reg .u64 t; cvta.to.shared.u64 t, %1; cvt.u32.u64 %0, t; }" : "=r"(r) : "l"(p));
    return r;
}
__device__ __forceinline__ void cpa16(u32 d, const void* s) {
    asm volatile("cp.async.cg.shared.global [%0], [%1], 16;" :: "r"(d), "l"(s));
}
__device__ __forceinline__ void cpa_commit() { asm volatile("cp.async.commit_group;" ::: "memory"); }
template <int W> __device__ __forceinline__ void cpa_wait() {
    asm volatile("cp.async.wait_group %0;" :: "n"(W) : "memory");
}
__device__ __forceinline__ void ldsm4(u32& r0, u32& r1, u32& r2, u32& r3, u32 a) {
    asm volatile("ldmatrix.sync.aligned.m8n8.x4.shared.b16 {%0,%1,%2,%3}, [%4];"
        : "=r"(r0), "=r"(r1), "=r"(r2), "=r"(r3) : "r"(a));
}
__device__ __forceinline__ void mma16816(float* d, const u32* a, const u32* b) {
    asm volatile("mma.sync.aligned.m16n8k16.row.col.f32.f16.f16.f32 "
        "{%0,%1,%2,%3},{%4,%5,%6,%7},{%8,%9},{%0,%1,%2,%3};"
        : "+f"(d[0]), "+f"(d[1]), "+f"(d[2]), "+f"(d[3])
        : "r"(a[0]), "r"(a[1]), "r"(a[2]), "r"(a[3]), "r"(b[0]), "r"(b[1]));
}
__device__ __forceinline__ u32 packh2(float a, float b) {
    fp16 h0 = __float2half_rn(a), h1 = __float2half_rn(b);
    return (u32)__half_as_ushort(h0) | ((u32)__half_as_ushort(h1) << 16);
}

// ---------------------------------------------------------------------------
// fp16 mma.sync GEMM: C[M,N] = A[M,K] * B[N,K]^T, fp32 accum.
// Block 128x128, BK=64 (128B swizzled rows), 8 warps x (64x32) warp tiles,
// 3-stage cp.async pipeline. grid=(N/128, M/128, batch).
// Epilogue: *scale (+bias) (relu) -> fp32 and/or fp16 outputs.
// ---------------------------------------------------------------------------
#define GTPB 256
#define NSTAGE 3
#define STG 32768                    // A 16K | B 16K
#define SMEM_TOTAL (NSTAGE * STG)    // 96 KB

__global__ void __launch_bounds__(GTPB, 2) gemm_mma(
    const fp16* __restrict__ A, const fp16* __restrict__ B,
    const float* __restrict__ bias,
    float* __restrict__ outF, fp16* __restrict__ outH,
    int N, int K, long long sA, long long sB, long long sC,
    float scale, int relu)
{
    extern __shared__ __align__(1024) char smem[];
    const u32 sb = smem_u32(smem);
    const int tid = threadIdx.x;
    const int wid = tid >> 5, lane = tid & 31;

    const long long zb = blockIdx.z;
    const long long rowBase = (long long)blockIdx.y * 128;
    const long long colBase = (long long)blockIdx.x * 128;
    const fp16* Ar = A + zb * sA + rowBase * K;
    const fp16* Br = B + zb * sB + colBase * K;
    const int nt = K >> 6;

    // fill one 32KB stage: A,B tiles 128 rows x 128B, 16B/cp.async, swizzled
    auto fill = [&](int t) {
        const u32 base = sb + (u32)(t % NSTAGE) * STG;
        const long long kof = (long long)t * 64;
#pragma unroll
        for (int i = 0; i < 4; i++) {
            const int c = tid + i * GTPB;          // 0..1023
            const int row = c >> 3, kc = c & 7;    // row 0..127, 16B col 0..7
            const u32 so = (u32)row * 128 + (((u32)kc * 16) ^ (((u32)row & 7) * 16));
            const long long g = (long long)row * K + kof + kc * 8;
            cpa16(base + so,         Ar + g);
            cpa16(base + 16384 + so, Br + g);
        }
    };

    fill(0); cpa_commit();
    fill(1); cpa_commit();

    float acc[4][4][4];
#pragma unroll
    for (int i = 0; i < 4; i++)
#pragma unroll
        for (int j = 0; j < 4; j++)
#pragma unroll
            for (int k = 0; k < 4; k++) acc[i][j][k] = 0.0f;

    const int mw = (wid >> 2) * 64;   // warp row offset (2 groups)
    const int nw = (wid & 3) * 32;    // warp col offset (4 groups)

    for (int t = 0; t < nt; t++) {
        if (t + 1 < nt) cpa_wait<1>(); else cpa_wait<0>();
        __syncthreads();                       // stage t visible; prev stage free
        if (t + 2 < nt) { fill(t + 2); cpa_commit(); }

        const u32 base = sb + (u32)(t % NSTAGE) * STG;
#pragma unroll
        for (int k16 = 0; k16 < 4; k16++) {
            const u32 kb = (u32)k16 * 32;      // byte col of this k16
            // A fragments: 4 m16 tiles
            u32 a[4][4];
#pragma unroll
            for (int mi = 0; mi < 4; mi++) {
                const u32 row = (u32)(mw + mi * 16 + (lane & 15));
                const u32 kbyte = kb + ((u32)(lane >> 4) << 4);
                const u32 ad = base + row * 128 + (kbyte ^ ((row & 7) << 4));
                ldsm4(a[mi][0], a[mi][1], a[mi][2], a[mi][3], ad);
            }
            // B fragments: 4 n8 tiles via 2 x4-loads
            u32 b[4][2];
#pragma unroll
            for (int nj = 0; nj < 2; nj++) {
                const u32 g = (u32)(lane >> 3);
                const u32 nrow = (u32)(nw + nj * 16) + ((g >> 1) << 3) + (u32)(lane & 7);
                const u32 kbyte = kb + ((g & 1) << 4);
                const u32 bd = base + 16384 + nrow * 128 + (kbyte ^ ((nrow & 7) << 4));
                u32 q0, q1, q2, q3;
                ldsm4(q0, q1, q2, q3, bd);
                b[nj*2][0] = q0; b[nj*2][1] = q1; b[nj*2+1][0] = q2; b[nj*2+1][1] = q3;
            }
            // 16 MMAs
#pragma unroll
            for (int mi = 0; mi < 4; mi++)
#pragma unroll
                for (int ni = 0; ni < 4; ni++) mma16816(acc[mi][ni], a[mi], b[ni]);
        }
    }

    // ---- epilogue ----
    float* ofz = outF ? outF + zb * sC : (float*)0;
    fp16*  ohz = outH ? outH + zb * sC : (fp16*)0;
#pragma unroll
    for (int mi = 0; mi < 4; mi++) {
#pragma unroll
        for (int ni = 0; ni < 4; ni++) {
            const long long r0 = rowBase + mw + mi * 16 + (lane >> 2);
            const long long c0 = colBase + nw + ni * 8 + (lane & 3) * 2;
            float b0 = 0.0f, b1 = 0.0f;
            if (bias) { b0 = __ldg(bias + c0); b1 = __ldg(bias + c0 + 1); }
#pragma unroll
            for (int h = 0; h < 2; h++) {
                float v0 = acc[mi][ni][2*h]   * scale + b0;
                float v1 = acc[mi][ni][2*h+1] * scale + b1;
                if (relu) { v0 = fmaxf(v0, 0.0f); v1 = fmaxf(v1, 0.0f); }
                const long long off = (r0 + 8 * h) * N + c0;
                if (ofz) *(float2*)(ofz + off) = make_float2(v0, v1);
                if (ohz) *(u32*)(ohz + off) = packh2(v0, v1);
            }
        }
    }
}

// ---------------- elementwise kernels --------------------------------------
__global__ void __launch_bounds__(256) cvt_plain(
    const float4* __restrict__ in, fp16* __restrict__ o, int n4)
{
    const int i = blockIdx.x * 256 + threadIdx.x;
    if (i >= n4) return;
    float4 x = in[i];
    *(uint2*)(o + 4 * (size_t)i) = make_uint2(packh2(x.x, x.y), packh2(x.z, x.w));
}

// in [R,C] fp32 -> out [C,R] fp16. grid (C/32, R/32, batch), 256 thr.
__global__ void __launch_bounds__(256) transpose_cvt(
    const float* __restrict__ in, fp16* __restrict__ o,
    int R, int C, long long sIn, long long sOut)
{
    __shared__ float t[32][33];
    in += (long long)blockIdx.z * sIn;
    o  += (long long)blockIdx.z * sOut;
    const int r0 = blockIdx.y * 32, c0 = blockIdx.x * 32;
    const int tx = threadIdx.x & 31, ty = threadIdx.x >> 5;
#pragma unroll
    for (int i = 0; i < 32; i += 8)
        t[ty + i][tx] = in[(long long)(r0 + ty + i) * C + c0 + tx];
    __syncthreads();
#pragma unroll
    for (int i = 0; i < 32; i += 8)
        o[(long long)(c0 + ty + i) * R + r0 + tx] = __float2half_rn(t[tx][ty + i]);
}

// row softmax over 2048 -> fp16. grid = nrows, block = 256.
__global__ void __launch_bounds__(256) softmax_h(
    const float* __restrict__ S, fp16* __restrict__ P)
{
    const float* p = S + (size_t)blockIdx.x * 2048;
    fp16* ph = P + (size_t)blockIdx.x * 2048;
    const int tid = threadIdx.x;
    __shared__ float red[8];
    float v[8], m = -1e30f;
#pragma unroll
    for (int i = 0; i < 8; i++) { v[i] = p[tid + 256 * i]; m = fmaxf(m, v[i]); }
#pragma unroll
    for (int o = 16; o > 0; o >>= 1) m = fmaxf(m, __shfl_xor_sync(~0u, m, o));
    if ((tid & 31) == 0) red[tid >> 5] = m;
    __syncthreads();
    m = red[0];
#pragma unroll
    for (int i = 1; i < 8; i++) m = fmaxf(m, red[i]);
    float s = 0.0f;
#pragma unroll
    for (int i = 0; i < 8; i++) { v[i] = expf(v[i] - m); s += v[i]; }
#pragma unroll
    for (int o = 16; o > 0; o >>= 1) s += __shfl_xor_sync(~0u, s, o);
    __syncthreads();
    if ((tid & 31) == 0) red[tid >> 5] = s;
    __syncthreads();
    s = red[0]+red[1]+red[2]+red[3]+red[4]+red[5]+red[6]+red[7];
    const float inv = 1.0f / s;
#pragma unroll
    for (int i = 0; i < 8; i++)
        ph[tid + 256 * i] = __float2half_rn(v[i] * inv);
}

// out = LN(A+B)*g+be (fp32, optional fp16). grid = nrows (width 1024).
__global__ void __launch_bounds__(256) add_ln(
    const float* __restrict__ A, const float* __restrict__ Bv,
    const float* __restrict__ g, const float* __restrict__ be,
    float* __restrict__ outF, fp16* __restrict__ oh)
{
    const size_t base = (size_t)blockIdx.x * 1024;
    const int tid = threadIdx.x;
    __shared__ float r1[8], r2[8];
    float v[4], s = 0.0f, ss = 0.0f;
#pragma unroll
    for (int i = 0; i < 4; i++) {
        const int c = tid + 256 * i;
        v[i] = A[base + c] + Bv[base + c];
        s += v[i]; ss += v[i] * v[i];
    }
#pragma unroll
    for (int o = 16; o > 0; o >>= 1) {
        s  += __shfl_xor_sync(~0u, s, o);
        ss += __shfl_xor_sync(~0u, ss, o);
    }
    if ((tid & 31) == 0) { r1[tid >> 5] = s; r2[tid >> 5] = ss; }
    __syncthreads();
    s = 0.0f; ss = 0.0f;
#pragma unroll
    for (int i = 0; i < 8; i++) { s += r1[i]; ss += r2[i]; }
    const float mean = s * (1.0f / 1024.0f);
    const float rstd = rsqrtf(ss * (1.0f / 1024.0f) - mean * mean + 1e-5f);
#pragma unroll
    for (int i = 0; i < 4; i++) {
        const int c = tid + 256 * i;
        const float x = (v[i] - mean) * rstd * g[c] + be[c];
        outF[base + c] = x;
        if (oh) oh[base + c] = __float2half_rn(x);
    }
}

// ---------------------------------------------------------------------------
extern "C" void kernel_launch(void* const* d_in, const int* in_sizes, int n_in,
                              void* d_out, int out_size)
{
    (void)in_sizes; (void)n_in; (void)out_size;
    const float* x   = (const float*)d_in[0];
    const float* wq  = (const float*)d_in[1];  const float* bq = (const float*)d_in[2];
    const float* wk  = (const float*)d_in[3];  const float* bk = (const float*)d_in[4];
    const float* wv  = (const float*)d_in[5];  const float* bv = (const float*)d_in[6];
    const float* wo  = (const float*)d_in[7];  const float* bo = (const float*)d_in[8];
    const float* w1  = (const float*)d_in[9];  const float* b1 = (const float*)d_in[10];
    const float* w2  = (const float*)d_in[11]; const float* b2 = (const float*)d_in[12];
    const float* g1  = (const float*)d_in[13]; const float* be1 = (const float*)d_in[14];
    const float* g2  = (const float*)d_in[15]; const float* be2 = (const float*)d_in[16];
    float* out = (float*)d_out;

#define SYM(nm, s) void* nm; cudaGetSymbolAddress(&nm, s)
    SYM(x16, g_x16);
    SYM(wq16, g_wq16); SYM(wk16, g_wk16); SYM(wv16, g_wv16); SYM(wo16, g_wo16);
    SYM(w116, g_w116); SYM(w216, g_w216);
    SYM(q16, g_q16); SYM(k16, g_k16);
    SYM(v, g_v); SYM(vt16, g_vt16);
    SYM(sc, g_sc); SYM(P16, g_P16);
    SYM(c16, g_c16);
    SYM(ao, g_ao); SYM(x1, g_x1); SYM(x116, g_x116);
    SYM(h16, g_h16); SYM(ffo, g_ffo);
#undef SYM
#define Fo(p) ((float*)p)
#define Hp(p) ((fp16*)p)

    cudaFuncSetAttribute(gemm_mma, cudaFuncAttributeMaxDynamicSharedMemorySize, SMEM_TOTAL);

    // operand prep: x -> fp16; weights transposed -> [N,K] fp16
    cvt_plain<<<MM * DD / 4 / 256, 256>>>((const float4*)x, Hp(x16), MM * DD / 4);
    transpose_cvt<<<dim3(DD/32, DD/32, 1), 256>>>(wq, Hp(wq16), DD, DD, 0, 0);
    transpose_cvt<<<dim3(DD/32, DD/32, 1), 256>>>(wk, Hp(wk16), DD, DD, 0, 0);
    transpose_cvt<<<dim3(DD/32, DD/32, 1), 256>>>(wv, Hp(wv16), DD, DD, 0, 0);
    transpose_cvt<<<dim3(DD/32, DD/32, 1), 256>>>(wo, Hp(wo16), DD, DD, 0, 0);
    transpose_cvt<<<dim3(FF/32, DD/32, 1), 256>>>(w1, Hp(w116), DD, FF, 0, 0);
    transpose_cvt<<<dim3(DD/32, FF/32, 1), 256>>>(w2, Hp(w216), FF, DD, 0, 0);

    const dim3 gq(DD/128, MM/128, 1);
    // QKV projections (Q,K -> fp16; V -> fp32 then transpose to fp16)
    gemm_mma<<<gq, GTPB, SMEM_TOTAL>>>(Hp(x16), Hp(wq16), bq,
        (float*)0, Hp(q16), DD, DD, 0, 0, 0, 1.0f, 0);
    gemm_mma<<<gq, GTPB, SMEM_TOTAL>>>(Hp(x16), Hp(wk16), bk,
        (float*)0, Hp(k16), DD, DD, 0, 0, 0, 1.0f, 0);
    gemm_mma<<<gq, GTPB, SMEM_TOTAL>>>(Hp(x16), Hp(wv16), bv,
        Fo(v), (fp16*)0, DD, DD, 0, 0, 0, 1.0f, 0);
    transpose_cvt<<<dim3(DD/32, SS/32, BB), 256>>>(Fo(v), Hp(vt16),
        SS, DD, (long long)SS*DD, (long long)SS*DD);

    // scores = Q K^T / 32
    gemm_mma<<<dim3(SS/128, SS/128, BB), GTPB, SMEM_TOTAL>>>(
        Hp(q16), Hp(k16), (const float*)0,
        Fo(sc), (fp16*)0, SS, DD,
        (long long)SS*DD, (long long)SS*DD, (long long)SS*SS, 0.03125f, 0);

    softmax_h<<<BB * SS, 256>>>(Fo(sc), Hp(P16));

    // ctx = P @ V   (B = V^T [D,S])
    gemm_mma<<<dim3(DD/128, SS/128, BB), GTPB, SMEM_TOTAL>>>(
        Hp(P16), Hp(vt16), (const float*)0,
        (float*)0, Hp(c16), DD, SS,
        (long long)SS*SS, (long long)SS*DD, (long long)SS*DD, 1.0f, 0);

    // attn_out = ctx @ Wo + bo
    gemm_mma<<<gq, GTPB, SMEM_TOTAL>>>(Hp(c16), Hp(wo16), bo,
        Fo(ao), (fp16*)0, DD, DD, 0, 0, 0, 1.0f, 0);

    // x1 = LN(x + attn_out)
    add_ln<<<MM, 256>>>(x, Fo(ao), g1, be1, Fo(x1), Hp(x116));

    // h = relu(x1 @ W1 + b1)
    gemm_mma<<<dim3(FF/128, MM/128, 1), GTPB, SMEM_TOTAL>>>(
        Hp(x116), Hp(w116), b1,
        (float*)0, Hp(h16), FF, DD, 0, 0, 0, 1.0f, 1);

    // ff = h @ W2 + b2
    gemm_mma<<<gq, GTPB, SMEM_TOTAL>>>(Hp(h16), Hp(w216), b2,
        Fo(ffo), (fp16*)0, DD, FF, 0, 0, 0, 1.0f, 0);

    // out = LN(x1 + ff)
    add_ln<<<MM, 256>>>(Fo(x1), Fo(ffo), g2, be2, out, (fp16*)0);
}